// round 15
// baseline (speedup 1.0000x reference)
#include <cuda_runtime.h>
#include <cuda_bf16.h>
#include <cuda_fp16.h>
#include <math.h>
#include <stdint.h>

// ---------------------------------------------------------------- constants
#define NPTS (4096 * 64)
#define NRAYS 4096
#define HASH_MASK 2097151u
#define P1H 2654435761u
#define P2H 805459861u

#define TILE_M 128
#define NTILES (NPTS / TILE_M)   // 2048
#define NCHUNK 26                 // 9 (gemm1) + 8 (gemm2 X) + 9 (gemm2 bott)

// ---------------- fused kernel smem layout (bytes) ----------------
#define XSTRIDE 264
#define BSTRIDE 296
#define SB_X    0
#define U2_OFF  0
#define SB_BOTT 67584
#define FE_OFF  67584
#define H_OFF   81920
#define U1_OFF  100352
#define SB_W    143360
#define WBUF_B  20480
#define SB_BIAS 225280
#define SMEMF_BYTES (SB_BIAS + 6672)    // 231952

#define BI_SB1  0
#define BI_SB2  64
#define BI_B0   320
#define BI_B1   576
#define BI_RW   832
#define BI_RB   1600
#define BI_DE   1604

// ---------------------------------------------------------------- globals
__device__ __half g_feats[(size_t)NPTS * 40];
__device__ __nv_bfloat16 g_W0T[256 * 288];
__device__ __nv_bfloat16 g_W1T[256 * 544];
__device__ __half g_U1T[64 * 48];
__device__ __half g_U2T[256 * 64];
__constant__ int c_offs[10] = {0, 4096, 36864, 299008, 2396160,
                               4493312, 6590464, 8687616, 10784768, 12881920};

// ---------------------------------------------------------------- helpers
__device__ __forceinline__ uint32_t bf16pack(float lo, float hi) {
    uint32_t d;
    asm("cvt.rn.bf16x2.f32 %0, %1, %2;" : "=r"(d) : "f"(hi), "f"(lo));
    return d;
}
__device__ __forceinline__ uint32_t h16pack(float lo, float hi) {
    uint32_t d;
    asm("cvt.rn.f16x2.f32 %0, %1, %2;" : "=r"(d) : "f"(hi), "f"(lo));
    return d;
}
__device__ __forceinline__ void mma_f16(float c[4],
    uint32_t a0, uint32_t a1, uint32_t a2, uint32_t a3,
    uint32_t b0, uint32_t b1)
{
    asm volatile(
        "mma.sync.aligned.m16n8k16.row.col.f32.f16.f16.f32 "
        "{%0,%1,%2,%3},{%4,%5,%6,%7},{%8,%9},{%0,%1,%2,%3};"
        : "+f"(c[0]), "+f"(c[1]), "+f"(c[2]), "+f"(c[3])
        : "r"(a0), "r"(a1), "r"(a2), "r"(a3), "r"(b0), "r"(b1));
}
__device__ __forceinline__ void mma_bf16(float c[4],
    uint32_t a0, uint32_t a1, uint32_t a2, uint32_t a3,
    uint32_t b0, uint32_t b1)
{
    asm volatile(
        "mma.sync.aligned.m16n8k16.row.col.f32.bf16.bf16.f32 "
        "{%0,%1,%2,%3},{%4,%5,%6,%7},{%8,%9},{%0,%1,%2,%3};"
        : "+f"(c[0]), "+f"(c[1]), "+f"(c[2]), "+f"(c[3])
        : "r"(a0), "r"(a1), "r"(a2), "r"(a3), "r"(b0), "r"(b1));
}
#define LDSM4(r, a) \
    asm volatile("ldmatrix.sync.aligned.m8n8.x4.shared.b16 {%0,%1,%2,%3}, [%4];" \
        : "=r"((r)[0]), "=r"((r)[1]), "=r"((r)[2]), "=r"((r)[3]) : "r"(a))
__device__ __forceinline__ uint32_t smem_u32(const void* p) {
    uint32_t a;
    asm("{ .reg .u64 t; cvta.to.shared.u64 t, %1; cvt.u32.u64 %0, t; }"
        : "=r"(a) : "l"(p));
    return a;
}
#define CP16(d, s) asm volatile("cp.async.cg.shared.global [%0], [%1], 16;" :: "r"(d), "l"(s))
#define CPCOMMIT() asm volatile("cp.async.commit_group;")
#define CPWAIT3()  asm volatile("cp.async.wait_group 3;" ::: "memory")
#define CPWAIT2()  asm volatile("cp.async.wait_group 2;" ::: "memory")
#define CPWAIT1()  asm volatile("cp.async.wait_group 1;" ::: "memory")
#define CPWAIT0()  asm volatile("cp.async.wait_group 0;" ::: "memory")
#define STS_ZERO16(a) asm volatile("st.shared.v4.u32 [%0], {%1,%1,%1,%1};" :: "r"(a), "r"(0u) : "memory")

// ---------------------------------------------------------------- prepW
__global__ void __launch_bounds__(256) prepW(
    const float* __restrict__ l0, const float* __restrict__ l1,
    const float* __restrict__ w1, const float* __restrict__ w2,
    __nv_bfloat16* __restrict__ W0T, __nv_bfloat16* __restrict__ W1T,
    __half* __restrict__ U1T, __half* __restrict__ U2T)
{
    int idx = blockIdx.x * 256 + threadIdx.x;
    if (idx < 256 * 288) {
        int n = idx / 288, k = idx % 288;
        W0T[idx] = __float2bfloat16((k < 283) ? l0[k * 256 + n] : 0.0f);
    }
    if (idx < 256 * 544) {
        int n = idx / 544, k = idx % 544;
        W1T[idx] = __float2bfloat16((k < 539) ? l1[k * 256 + n] : 0.0f);
    }
    if (idx < 64 * 48) {
        int n = idx / 48, k = idx % 48;
        U1T[idx] = __float2half((k < 40) ? w1[k * 64 + n] : 0.0f);
    }
    if (idx < 256 * 64) {
        int n = idx / 64, k = idx % 64;
        U2T[idx] = __float2half(w2[k * 256 + n]);
    }
}

// ---------------------------------------------------------------- kernel A
// gather only; 2 threads per point (5 levels each); fp16 output; batched half
__global__ void __launch_bounds__(256) kernA(
    const float* __restrict__ coords,
    const float4* __restrict__ emb,
    __half* __restrict__ feats,
    int pid_base)
{
    const int t = threadIdx.x;
    const int pid = pid_base + blockIdx.x * 128 + (t & 127);
    const int half_ = t >> 7;   // 0: levels 0-4, 1: levels 5-9

    float cx = coords[pid * 3 + 0];
    float cy = coords[pid * 3 + 1];
    float cz = coords[pid * 3 + 2];
    float nn = sqrtf(cx * cx + cy * cy + cz * cz);
    nn = fmaxf(nn, 1.1920929e-7f);
    if (nn > 1.0f) {
        float sc = 2.0f - 1.0f / nn;
        cx = sc * (cx / nn); cy = sc * (cy / nn); cz = sc * (cz / nn);
    }
    const float ux = (cx * 0.5f + 1.0f) * 0.5f;
    const float uy = (cy * 0.5f + 1.0f) * 0.5f;
    const float uz = (cz * 0.5f + 1.0f) * 0.5f;

    const int l0 = half_ * 5;
    uint2* out = (uint2*)(feats + (size_t)pid * 40 + l0 * 4);

#pragma unroll
    for (int li = 0; li < 5; li++) {
        const int l = l0 + li;
        const int res = 16 << l;
        const float s = (float)res - 1.0f;
        float px = ux * s + 0.5f, py = uy * s + 0.5f, pz = uz * s + 0.5f;
        float gxf = floorf(px), gyf = floorf(py), gzf = floorf(pz);
        float fx = px - gxf, fy = py - gyf, fz = pz - gzf;
        int gx = (int)gxf, gy = (int)gyf, gz = (int)gzf;
        float f0 = 0, f1 = 0, f2 = 0, f3 = 0;
        const int off = c_offs[l];
        const bool dense = (l < 4);
#pragma unroll
        for (int c = 0; c < 8; c++) {
            const int b0 = c & 1, b1c = (c >> 1) & 1, b2c = (c >> 2) & 1;
            float w = (b0 ? fx : 1.0f - fx) * (b1c ? fy : 1.0f - fy)
                    * (b2c ? fz : 1.0f - fz);
            int idx;
            if (dense) {
                idx = (gx + b0) + (gy + b1c) * res + (gz + b2c) * res * res;
            } else {
                idx = (int)(((uint32_t)(gx + b0)
                           ^ ((uint32_t)(gy + b1c) * P1H)
                           ^ ((uint32_t)(gz + b2c) * P2H)) & HASH_MASK);
            }
            float4 e = __ldg(&emb[off + idx]);
            f0 += w * e.x; f1 += w * e.y; f2 += w * e.z; f3 += w * e.w;
        }
        out[li] = make_uint2(h16pack(f0, f1), h16pack(f2, f3));
    }
}

// ---------------------------------------------------------------- fused kernel
__global__ void __launch_bounds__(512, 1) kernF(
    const __half* __restrict__ feats,
    const float* __restrict__ viewdirs,
    const __half* __restrict__ U1Tg, const __half* __restrict__ U2Tg,
    const float* __restrict__ sb1g, const float* __restrict__ sb2g,
    const __nv_bfloat16* __restrict__ W0T, const __nv_bfloat16* __restrict__ W1T,
    const float* __restrict__ b0g, const float* __restrict__ b1g,
    const float* __restrict__ rgbwg, const float* __restrict__ rgbbg,
    float* __restrict__ density, float* __restrict__ out_rgb,
    int tile_base)
{
    extern __shared__ char smem[];
    const uint32_t sb = smem_u32(smem);
    float* bias = (float*)(smem + SB_BIAS);
    __half* FEh = (__half*)(smem + FE_OFF);   // [128][56]
    __half* Hh  = (__half*)(smem + H_OFF);    // [128][72]
    __half* U1h = (__half*)(smem + U1_OFF);   // [64][56]
    __half* U2h = (__half*)(smem + U2_OFF);   // [256][72]
    __nv_bfloat16* Xp = (__nv_bfloat16*)(smem + SB_X);     // [128][264]
    __nv_bfloat16* Bp = (__nv_bfloat16*)(smem + SB_BOTT);  // [128][296]

    const int t = threadIdx.x;
    const int wid = t >> 5, lane = t & 31;
    const int g = lane >> 2, tq = lane & 3;
    const size_t base = (size_t)(tile_base + blockIdx.x) * TILE_M;

    // ---- phase 0: small data + pads ----
    if (t < 64)  bias[BI_SB1 + t] = sb1g[t];
    if (t >= 64 && t < 320) bias[BI_SB2 + t - 64] = sb2g[t - 64];
    if (t < 256) { bias[BI_B0 + t] = b0g[t]; bias[BI_B1 + t] = b1g[t]; }
    for (int i = t; i < 768; i += 512) bias[BI_RW + i] = rgbwg[i];
    if (t < 3) bias[BI_RB + t] = rgbbg[t];
    if (t < 64) {
        int ray = (int)(base >> 6) + (t >> 5);
        int i = t & 31;
        float v = 0.0f;
        if (i < 27) {
            float dx = viewdirs[ray * 3 + 0];
            float dy = viewdirs[ray * 3 + 1];
            float dz = viewdirs[ray * 3 + 2];
            if (i < 3) v = (i == 0) ? dx : ((i == 1) ? dy : dz);
            else {
                int j = i - 3, deg = j / 6, rem = j % 6;
                float d = ((rem % 3) == 0) ? dx : (((rem % 3) == 1) ? dy : dz);
                float xb = d * (float)(1 << deg);
                v = (rem < 3) ? sinf(xb) : sinf(xb + 1.5707964f);
            }
        }
        bias[BI_DE + (t >> 5) * 32 + i] = v;
    }
    if (t < 128) STS_ZERO16(sb + FE_OFF + (uint32_t)(t * 112 + 80));

    // ---- phase 0: cp.async group G0 (feats, U1, U2 — all fp16) ----
    for (int i = t; i < 128 * 5; i += 512) {
        int r = i / 5, s = i % 5;
        CP16(sb + FE_OFF + (uint32_t)(r * 112 + s * 16),
             feats + (base + (size_t)r) * 40 + s * 8);
    }
    for (int i = t; i < 64 * 6; i += 512) {
        int r = i / 6, s = i % 6;
        CP16(sb + U1_OFF + (uint32_t)(r * 112 + s * 16), U1Tg + (size_t)r * 48 + s * 8);
    }
#pragma unroll
    for (int j = 0; j < 4; j++) {
        int i = t + 512 * j;
        int r = i >> 3, s = i & 7;
        CP16(sb + U2_OFF + (uint32_t)(r * 144 + s * 16), U2Tg + (size_t)r * 64 + s * 8);
    }
    CPCOMMIT();

    auto issueW = [&](int p) {
        const uint32_t wbase = sb + SB_W + (uint32_t)(p & 3) * WBUF_B;
        const __nv_bfloat16* wsrc; int wld, wcol;
        if (p < 9)       { wsrc = W0T; wld = 288; wcol = p * 32; }
        else if (p < 17) { wsrc = W1T; wld = 544; wcol = (p - 9) * 32; }
        else             { wsrc = W1T; wld = 544; wcol = 256 + (p - 17) * 32; }
#pragma unroll
        for (int j = 0; j < 2; j++) {
            int i = t + 512 * j, row = i >> 2, seg = i & 3;
            CP16(wbase + (uint32_t)row * 80u + (uint32_t)seg * 16u,
                 wsrc + (size_t)row * wld + wcol + seg * 8);
        }
    };
    issueW(0); CPCOMMIT();
    issueW(1); CPCOMMIT();
    issueW(2); CPCOMMIT();

    CPWAIT3();
    __syncthreads();

    // ---- phase 1: GEMM0a (fp16): h = relu(feats @ U1 + sb1), K=48, N=64 ----
    {
        const int m0a = (wid & 3) * 32, n0a = (wid >> 2) * 16;
        float acc0[2][2][4];
#pragma unroll
        for (int mf = 0; mf < 2; mf++)
#pragma unroll
            for (int nf = 0; nf < 2; nf++) {
                int col = n0a + nf * 8 + tq * 2;
                acc0[mf][nf][0] = bias[BI_SB1 + col];
                acc0[mf][nf][1] = bias[BI_SB1 + col + 1];
                acc0[mf][nf][2] = bias[BI_SB1 + col];
                acc0[mf][nf][3] = bias[BI_SB1 + col + 1];
            }
#pragma unroll
        for (int ks = 0; ks < 3; ks++) {
            const int kk = ks * 16;
            uint32_t a[2][4], b[2][2];
#pragma unroll
            for (int mf = 0; mf < 2; mf++) {
                const __half* ap = FEh + (m0a + mf * 16 + g) * 56 + kk + tq * 2;
                a[mf][0] = *(const uint32_t*)ap;
                a[mf][1] = *(const uint32_t*)(ap + 8 * 56);
                a[mf][2] = *(const uint32_t*)(ap + 8);
                a[mf][3] = *(const uint32_t*)(ap + 8 * 56 + 8);
            }
#pragma unroll
            for (int nf = 0; nf < 2; nf++) {
                const __half* bp = U1h + (n0a + nf * 8 + g) * 56 + kk + tq * 2;
                b[nf][0] = *(const uint32_t*)bp;
                b[nf][1] = *(const uint32_t*)(bp + 8);
            }
#pragma unroll
            for (int mf = 0; mf < 2; mf++)
#pragma unroll
                for (int nf = 0; nf < 2; nf++)
                    mma_f16(acc0[mf][nf], a[mf][0], a[mf][1], a[mf][2], a[mf][3],
                            b[nf][0], b[nf][1]);
        }
        __syncthreads();
#pragma unroll
        for (int mf = 0; mf < 2; mf++) {
            const int r0 = m0a + mf * 16 + g;
#pragma unroll
            for (int nf = 0; nf < 2; nf++) {
                const int col = n0a + nf * 8 + tq * 2;
                *(uint32_t*)(Hh + r0 * 72 + col) =
                    h16pack(fmaxf(acc0[mf][nf][0], 0.0f), fmaxf(acc0[mf][nf][1], 0.0f));
                *(uint32_t*)(Hh + (r0 + 8) * 72 + col) =
                    h16pack(fmaxf(acc0[mf][nf][2], 0.0f), fmaxf(acc0[mf][nf][3], 0.0f));
            }
        }
    }
    __syncthreads();

    // ---- phase 2: GEMM0b (fp16): bott = h @ U2 + sb2 -> BOTT bf16 ----
    const int wm = wid & 1, wn = wid >> 1;
    const int m0 = wm * 64, n0 = wn * 32;
    float acc[4][4][4];
#pragma unroll
    for (int mf = 0; mf < 4; mf++)
#pragma unroll
        for (int nf = 0; nf < 4; nf++) {
            int col = n0 + nf * 8 + tq * 2;
            acc[mf][nf][0] = bias[BI_SB2 + col];
            acc[mf][nf][1] = bias[BI_SB2 + col + 1];
            acc[mf][nf][2] = bias[BI_SB2 + col];
            acc[mf][nf][3] = bias[BI_SB2 + col + 1];
        }
#pragma unroll
    for (int ks = 0; ks < 4; ks++) {
        const int kk = ks * 16;
        uint32_t a[4][4], b[4][2];
#pragma unroll
        for (int mf = 0; mf < 4; mf++) {
            const __half* ap = Hh + (m0 + mf * 16 + g) * 72 + kk + tq * 2;
            a[mf][0] = *(const uint32_t*)ap;
            a[mf][1] = *(const uint32_t*)(ap + 8 * 72);
            a[mf][2] = *(const uint32_t*)(ap + 8);
            a[mf][3] = *(const uint32_t*)(ap + 8 * 72 + 8);
        }
#pragma unroll
        for (int nf = 0; nf < 4; nf++) {
            const __half* bp = U2h + (n0 + nf * 8 + g) * 72 + kk + tq * 2;
            b[nf][0] = *(const uint32_t*)bp;
            b[nf][1] = *(const uint32_t*)(bp + 8);
        }
#pragma unroll
        for (int mf = 0; mf < 4; mf++)
#pragma unroll
            for (int nf = 0; nf < 4; nf++)
                mma_f16(acc[mf][nf], a[mf][0], a[mf][1], a[mf][2], a[mf][3],
                        b[nf][0], b[nf][1]);
    }
    __syncthreads();

    // epilogue 0b: BOTT bf16 cols 0..255 + density; direnc cols 256..287
#pragma unroll
    for (int mf = 0; mf < 4; mf++) {
        const int r0 = m0 + mf * 16 + g;
#pragma unroll
        for (int nf = 0; nf < 4; nf++) {
            const int col = n0 + nf * 8 + tq * 2;
            *(uint32_t*)(Bp + r0 * BSTRIDE + col)       = bf16pack(acc[mf][nf][0], acc[mf][nf][1]);
            *(uint32_t*)(Bp + (r0 + 8) * BSTRIDE + col) = bf16pack(acc[mf][nf][2], acc[mf][nf][3]);
        }
        if (wn == 0 && tq == 0) {
            float r = acc[mf][0][0] - 1.0f;
            density[base + r0] = (r > 0.0f) ? (r + log1pf(expf(-r))) : log1pf(expf(r));
            r = acc[mf][0][2] - 1.0f;
            density[base + r0 + 8] = (r > 0.0f) ? (r + log1pf(expf(-r))) : log1pf(expf(r));
        }
    }
#pragma unroll
    for (int j = 0; j < 4; j++) {
        int i = t + 512 * j;
        int row = i >> 4, q = i & 15;
        const float* de = &bias[BI_DE + (row >> 6) * 32];
        *(uint32_t*)(Bp + row * BSTRIDE + 256 + q * 2) = bf16pack(de[q * 2], de[q * 2 + 1]);
    }

    // re-init acc with b0 for GEMM1
#pragma unroll
    for (int mf = 0; mf < 4; mf++)
#pragma unroll
        for (int nf = 0; nf < 4; nf++) {
            int col = n0 + nf * 8 + tq * 2;
            acc[mf][nf][0] = bias[BI_B0 + col];
            acc[mf][nf][1] = bias[BI_B0 + col + 1];
            acc[mf][nf][2] = bias[BI_B0 + col];
            acc[mf][nf][3] = bias[BI_B0 + col + 1];
        }

    // ---- phase 3: main loop, 26 chunks; 4-deep W ring, 2 chunks in flight ----
    const int arow = lane & 15;
    const int ak8  = ((lane >> 4) & 1) << 3;
    const int brow = ((lane >> 1) & 8) + (lane & 7);
    const int bk8  = lane & 8;

    for (int c = 0; c < NCHUNK; c++) {
        if (c <= NCHUNK - 3)      { CPWAIT2(); }
        else if (c == NCHUNK - 2) { CPWAIT1(); }
        else                      { CPWAIT0(); }
        __syncthreads();

        uint32_t aPane, astr; int k0;
        if (c < 9)       { aPane = sb + SB_BOTT; astr = BSTRIDE; k0 = c * 32; }
        else if (c < 17) { aPane = sb + SB_X;    astr = XSTRIDE; k0 = (c - 9) * 32; }
        else             { aPane = sb + SB_BOTT; astr = BSTRIDE; k0 = (c - 17) * 32; }
        const uint32_t wPane = sb + SB_W + (uint32_t)(c & 3) * WBUF_B;

#pragma unroll
        for (int ks = 0; ks < 2; ks++) {
            const int kk = k0 + ks * 16;
            uint32_t a[4][4], bb[2][4];
#pragma unroll
            for (int mf = 0; mf < 4; mf++) {
                uint32_t addr = aPane +
                    (uint32_t)(((m0 + mf * 16 + arow) * astr) + kk + ak8) * 2u;
                LDSM4(a[mf], addr);
            }
#pragma unroll
            for (int p = 0; p < 2; p++) {
                uint32_t addr = wPane +
                    (uint32_t)(((n0 + p * 16 + brow) * 40) + ks * 16 + bk8) * 2u;
                LDSM4(bb[p], addr);
            }
#pragma unroll
            for (int mf = 0; mf < 4; mf++)
#pragma unroll
                for (int p = 0; p < 2; p++) {
                    mma_bf16(acc[mf][p * 2 + 0], a[mf][0], a[mf][1], a[mf][2], a[mf][3],
                             bb[p][0], bb[p][1]);
                    mma_bf16(acc[mf][p * 2 + 1], a[mf][0], a[mf][1], a[mf][2], a[mf][3],
                             bb[p][2], bb[p][3]);
                }
        }

        if (c == 8) {
#pragma unroll
            for (int mf = 0; mf < 4; mf++) {
                const int r0 = m0 + mf * 16 + g;
#pragma unroll
                for (int nf = 0; nf < 4; nf++) {
                    const int col = n0 + nf * 8 + tq * 2;
                    *(uint32_t*)(Xp + r0 * XSTRIDE + col) =
                        bf16pack(fmaxf(acc[mf][nf][0], 0.0f), fmaxf(acc[mf][nf][1], 0.0f));
                    *(uint32_t*)(Xp + (r0 + 8) * XSTRIDE + col) =
                        bf16pack(fmaxf(acc[mf][nf][2], 0.0f), fmaxf(acc[mf][nf][3], 0.0f));
                    acc[mf][nf][0] = bias[BI_B1 + col];
                    acc[mf][nf][1] = bias[BI_B1 + col + 1];
                    acc[mf][nf][2] = bias[BI_B1 + col];
                    acc[mf][nf][3] = bias[BI_B1 + col + 1];
                }
            }
        }
        if (c + 3 < NCHUNK) issueW(c + 3);
        CPCOMMIT();
    }

    // ---- phase 4: rgb head ----
    float p[8][3];
#pragma unroll
    for (int r = 0; r < 8; r++) { p[r][0] = 0; p[r][1] = 0; p[r][2] = 0; }
#pragma unroll
    for (int mf = 0; mf < 4; mf++)
#pragma unroll
        for (int nf = 0; nf < 4; nf++) {
            const int col0 = n0 + nf * 8 + tq * 2, col1 = col0 + 1;
            float y00 = fmaxf(acc[mf][nf][0], 0.0f);
            float y01 = fmaxf(acc[mf][nf][1], 0.0f);
            float y10 = fmaxf(acc[mf][nf][2], 0.0f);
            float y11 = fmaxf(acc[mf][nf][3], 0.0f);
#pragma unroll
            for (int ch = 0; ch < 3; ch++) {
                float w0 = bias[BI_RW + col0 * 3 + ch], w1 = bias[BI_RW + col1 * 3 + ch];
                p[mf * 2 + 0][ch] += y00 * w0 + y01 * w1;
                p[mf * 2 + 1][ch] += y10 * w0 + y11 * w1;
            }
        }
#pragma unroll
    for (int r = 0; r < 8; r++)
#pragma unroll
        for (int ch = 0; ch < 3; ch++) {
            p[r][ch] += __shfl_xor_sync(0xffffffffu, p[r][ch], 1);
            p[r][ch] += __shfl_xor_sync(0xffffffffu, p[r][ch], 2);
        }

    float* part = (float*)(smem + SB_BOTT);
    __syncthreads();
    if (tq == 0) {
#pragma unroll
        for (int mf = 0; mf < 4; mf++)
#pragma unroll
            for (int h = 0; h < 2; h++) {
                int row = m0 + mf * 16 + g + 8 * h;
                int r = mf * 2 + h;
                part[(wn * 128 + row) * 3 + 0] = p[r][0];
                part[(wn * 128 + row) * 3 + 1] = p[r][1];
                part[(wn * 128 + row) * 3 + 2] = p[r][2];
            }
    }
    __syncthreads();
    if (t < 384) {
        const int m = t / 3, ch = t - m * 3;
        float v = bias[BI_RB + ch];
#pragma unroll
        for (int gq = 0; gq < 8; gq++) v += part[(gq * 128 + m) * 3 + ch];
        float sg = 1.0f / (1.0f + expf(-v));
        out_rgb[(base + (size_t)m) * 3 + ch] = sg * 1.002f - 0.001f;
    }
}

// ---------------------------------------------------------------- launch
extern "C" void kernel_launch(void* const* d_in, const int* in_sizes, int n_in,
                              void* d_out, int out_size)
{
    const float*  coords   = (const float*)d_in[0];
    const float*  viewdirs = (const float*)d_in[2];
    const float4* emb      = (const float4*)d_in[3];
    const float*  w1       = (const float*)d_in[4];
    const float*  b1       = (const float*)d_in[5];
    const float*  w2       = (const float*)d_in[6];
    const float*  b2       = (const float*)d_in[7];
    const float*  lin0_w   = (const float*)d_in[8];
    const float*  lin0_b   = (const float*)d_in[9];
    const float*  lin1_w   = (const float*)d_in[10];
    const float*  lin1_b   = (const float*)d_in[11];
    const float*  rgb_w    = (const float*)d_in[12];
    const float*  rgb_b    = (const float*)d_in[13];

    float* dout    = (float*)d_out;
    float* density = dout;
    float* rgb     = dout + NPTS;

    __half *feats, *U1T, *U2T;
    __nv_bfloat16 *W0T, *W1T;
    cudaGetSymbolAddress((void**)&feats, g_feats);
    cudaGetSymbolAddress((void**)&W0T, g_W0T);
    cudaGetSymbolAddress((void**)&W1T, g_W1T);
    cudaGetSymbolAddress((void**)&U1T, g_U1T);
    cudaGetSymbolAddress((void**)&U2T, g_U2T);

    cudaFuncSetAttribute(kernF, cudaFuncAttributeMaxDynamicSharedMemorySize,
                         SMEMF_BYTES);

    // lazily-created side stream + fork/join events (host objects only;
    // work performed per call is identical and deterministic)
    static cudaStream_t s2 = nullptr;
    static cudaEvent_t evRoot = nullptr, evA0 = nullptr, evA1 = nullptr,
                       evF = nullptr;
    if (s2 == nullptr) {
        cudaStreamCreateWithFlags(&s2, cudaStreamNonBlocking);
        cudaEventCreateWithFlags(&evRoot, cudaEventDisableTiming);
        cudaEventCreateWithFlags(&evA0, cudaEventDisableTiming);
        cudaEventCreateWithFlags(&evA1, cudaEventDisableTiming);
        cudaEventCreateWithFlags(&evF, cudaEventDisableTiming);
    }

    const int HALF_PTS   = NPTS / 2;      // 131072
    const int HALF_BLKA  = HALF_PTS / 128; // 1024
    const int HALF_TILES = NTILES / 2;     // 1024

    // fork s2 from the main stream
    cudaEventRecord(evRoot, 0);
    cudaStreamWaitEvent(s2, evRoot, 0);

    // s2: weight prep (only needed by kernF)
    prepW<<<544, 256, 0, s2>>>(lin0_w, lin1_w, w1, w2, W0T, W1T, U1T, U2T);

    // s0: gather halves
    kernA<<<HALF_BLKA, 256>>>(coords, emb, feats, 0);
    cudaEventRecord(evA0, 0);
    kernA<<<HALF_BLKA, 256>>>(coords, emb, feats, HALF_PTS);
    cudaEventRecord(evA1, 0);

    // s2: kernF halves (F0 after prepW+A0 — overlaps A1; F1 after A1)
    cudaStreamWaitEvent(s2, evA0, 0);
    kernF<<<HALF_TILES, 512, SMEMF_BYTES, s2>>>(
        feats, viewdirs, U1T, U2T, b1, b2, W0T, W1T, lin0_b, lin1_b,
        rgb_w, rgb_b, density, rgb, 0);
    cudaStreamWaitEvent(s2, evA1, 0);
    kernF<<<HALF_TILES, 512, SMEMF_BYTES, s2>>>(
        feats, viewdirs, U1T, U2T, b1, b2, W0T, W1T, lin0_b, lin1_b,
        rgb_w, rgb_b, density, rgb, HALF_TILES);

    // join back to the main stream
    cudaEventRecord(evF, s2);
    cudaStreamWaitEvent(0, evF, 0);
}

// round 16
// speedup vs baseline: 1.0634x; 1.0634x over previous
#include <cuda_runtime.h>
#include <cuda_bf16.h>
#include <cuda_fp16.h>
#include <math.h>
#include <stdint.h>

// ---------------------------------------------------------------- constants
#define NPTS (4096 * 64)
#define NRAYS 4096
#define HASH_MASK 2097151u
#define P1H 2654435761u
#define P2H 805459861u

#define TILE_M 128
#define NTILES (NPTS / TILE_M)   // 2048
#define NCHUNK 26                 // 9 (gemm1) + 8 (gemm2 X) + 9 (gemm2 bott)

// ---------------- fused kernel smem layout (bytes) ----------------
#define XSTRIDE 264
#define BSTRIDE 296
#define SB_X    0
#define U2_OFF  0
#define SB_BOTT 67584
#define FE_OFF  67584
#define H_OFF   81920
#define U1_OFF  100352
#define SB_W    143360
#define WBUF_B  20480
#define SB_BIAS 225280
#define SMEMF_BYTES (SB_BIAS + 6672)    // 231952

#define BI_SB1  0
#define BI_SB2  64
#define BI_B0   320
#define BI_B1   576
#define BI_RW   832
#define BI_RB   1600
#define BI_DE   1604

// ---------------------------------------------------------------- globals
__device__ __half g_feats[(size_t)NPTS * 40];
__device__ __nv_bfloat16 g_W0T[256 * 288];
__device__ __nv_bfloat16 g_W1T[256 * 544];
__device__ __half g_U1T[64 * 48];
__device__ __half g_U2T[256 * 64];
__constant__ int c_offs[10] = {0, 4096, 36864, 299008, 2396160,
                               4493312, 6590464, 8687616, 10784768, 12881920};

// ---------------------------------------------------------------- helpers
__device__ __forceinline__ uint32_t bf16pack(float lo, float hi) {
    uint32_t d;
    asm("cvt.rn.bf16x2.f32 %0, %1, %2;" : "=r"(d) : "f"(hi), "f"(lo));
    return d;
}
__device__ __forceinline__ uint32_t h16pack(float lo, float hi) {
    uint32_t d;
    asm("cvt.rn.f16x2.f32 %0, %1, %2;" : "=r"(d) : "f"(hi), "f"(lo));
    return d;
}
__device__ __forceinline__ void mma_f16(float c[4],
    uint32_t a0, uint32_t a1, uint32_t a2, uint32_t a3,
    uint32_t b0, uint32_t b1)
{
    asm volatile(
        "mma.sync.aligned.m16n8k16.row.col.f32.f16.f16.f32 "
        "{%0,%1,%2,%3},{%4,%5,%6,%7},{%8,%9},{%0,%1,%2,%3};"
        : "+f"(c[0]), "+f"(c[1]), "+f"(c[2]), "+f"(c[3])
        : "r"(a0), "r"(a1), "r"(a2), "r"(a3), "r"(b0), "r"(b1));
}
__device__ __forceinline__ void mma_bf16(float c[4],
    uint32_t a0, uint32_t a1, uint32_t a2, uint32_t a3,
    uint32_t b0, uint32_t b1)
{
    asm volatile(
        "mma.sync.aligned.m16n8k16.row.col.f32.bf16.bf16.f32 "
        "{%0,%1,%2,%3},{%4,%5,%6,%7},{%8,%9},{%0,%1,%2,%3};"
        : "+f"(c[0]), "+f"(c[1]), "+f"(c[2]), "+f"(c[3])
        : "r"(a0), "r"(a1), "r"(a2), "r"(a3), "r"(b0), "r"(b1));
}
#define LDSM4(r, a) \
    asm volatile("ldmatrix.sync.aligned.m8n8.x4.shared.b16 {%0,%1,%2,%3}, [%4];" \
        : "=r"((r)[0]), "=r"((r)[1]), "=r"((r)[2]), "=r"((r)[3]) : "r"(a))
__device__ __forceinline__ uint32_t smem_u32(const void* p) {
    uint32_t a;
    asm("{ .reg .u64 t; cvta.to.shared.u64 t, %1; cvt.u32.u64 %0, t; }"
        : "=r"(a) : "l"(p));
    return a;
}
#define CP16(d, s) asm volatile("cp.async.cg.shared.global [%0], [%1], 16;" :: "r"(d), "l"(s))
#define CPCOMMIT() asm volatile("cp.async.commit_group;")
#define CPWAIT3()  asm volatile("cp.async.wait_group 3;" ::: "memory")
#define CPWAIT2()  asm volatile("cp.async.wait_group 2;" ::: "memory")
#define CPWAIT1()  asm volatile("cp.async.wait_group 1;" ::: "memory")
#define CPWAIT0()  asm volatile("cp.async.wait_group 0;" ::: "memory")
#define STS_ZERO16(a) asm volatile("st.shared.v4.u32 [%0], {%1,%1,%1,%1};" :: "r"(a), "r"(0u) : "memory")

// ---------------------------------------------------------------- prepW
__global__ void __launch_bounds__(256) prepW(
    const float* __restrict__ l0, const float* __restrict__ l1,
    const float* __restrict__ w1, const float* __restrict__ w2,
    __nv_bfloat16* __restrict__ W0T, __nv_bfloat16* __restrict__ W1T,
    __half* __restrict__ U1T, __half* __restrict__ U2T)
{
    int idx = blockIdx.x * 256 + threadIdx.x;
    if (idx < 256 * 288) {
        int n = idx / 288, k = idx % 288;
        W0T[idx] = __float2bfloat16((k < 283) ? l0[k * 256 + n] : 0.0f);
    }
    if (idx < 256 * 544) {
        int n = idx / 544, k = idx % 544;
        W1T[idx] = __float2bfloat16((k < 539) ? l1[k * 256 + n] : 0.0f);
    }
    if (idx < 64 * 48) {
        int n = idx / 48, k = idx % 48;
        U1T[idx] = __float2half((k < 40) ? w1[k * 64 + n] : 0.0f);
    }
    if (idx < 256 * 64) {
        int n = idx / 64, k = idx % 64;
        U2T[idx] = __float2half(w2[k * 256 + n]);
    }
}

// ---------------------------------------------------------------- kernel A
// gather only; 2 threads per point (5 levels each); fp16 output
__global__ void __launch_bounds__(256) kernA(
    const float* __restrict__ coords,
    const float4* __restrict__ emb,
    __half* __restrict__ feats)
{
    const int t = threadIdx.x;
    const int pid = blockIdx.x * 128 + (t & 127);
    const int half_ = t >> 7;   // 0: levels 0-4, 1: levels 5-9

    float cx = coords[pid * 3 + 0];
    float cy = coords[pid * 3 + 1];
    float cz = coords[pid * 3 + 2];
    float nn = sqrtf(cx * cx + cy * cy + cz * cz);
    nn = fmaxf(nn, 1.1920929e-7f);
    if (nn > 1.0f) {
        float sc = 2.0f - 1.0f / nn;
        cx = sc * (cx / nn); cy = sc * (cy / nn); cz = sc * (cz / nn);
    }
    const float ux = (cx * 0.5f + 1.0f) * 0.5f;
    const float uy = (cy * 0.5f + 1.0f) * 0.5f;
    const float uz = (cz * 0.5f + 1.0f) * 0.5f;

    const int l0 = half_ * 5;
    uint2* out = (uint2*)(feats + (size_t)pid * 40 + l0 * 4);

#pragma unroll
    for (int li = 0; li < 5; li++) {
        const int l = l0 + li;
        const int res = 16 << l;
        const float s = (float)res - 1.0f;
        float px = ux * s + 0.5f, py = uy * s + 0.5f, pz = uz * s + 0.5f;
        float gxf = floorf(px), gyf = floorf(py), gzf = floorf(pz);
        float fx = px - gxf, fy = py - gyf, fz = pz - gzf;
        int gx = (int)gxf, gy = (int)gyf, gz = (int)gzf;
        float f0 = 0, f1 = 0, f2 = 0, f3 = 0;
        const int off = c_offs[l];
        const bool dense = (l < 4);
#pragma unroll
        for (int c = 0; c < 8; c++) {
            const int b0 = c & 1, b1c = (c >> 1) & 1, b2c = (c >> 2) & 1;
            float w = (b0 ? fx : 1.0f - fx) * (b1c ? fy : 1.0f - fy)
                    * (b2c ? fz : 1.0f - fz);
            int idx;
            if (dense) {
                idx = (gx + b0) + (gy + b1c) * res + (gz + b2c) * res * res;
            } else {
                idx = (int)(((uint32_t)(gx + b0)
                           ^ ((uint32_t)(gy + b1c) * P1H)
                           ^ ((uint32_t)(gz + b2c) * P2H)) & HASH_MASK);
            }
            float4 e = __ldg(&emb[off + idx]);
            f0 += w * e.x; f1 += w * e.y; f2 += w * e.z; f3 += w * e.w;
        }
        out[li] = make_uint2(h16pack(f0, f1), h16pack(f2, f3));
    }
}

// ---------------------------------------------------------------- fused kernel
__global__ void __launch_bounds__(512, 1) kernF(
    const __half* __restrict__ feats,
    const float* __restrict__ viewdirs,
    const __half* __restrict__ U1Tg, const __half* __restrict__ U2Tg,
    const float* __restrict__ sb1g, const float* __restrict__ sb2g,
    const __nv_bfloat16* __restrict__ W0T, const __nv_bfloat16* __restrict__ W1T,
    const float* __restrict__ b0g, const float* __restrict__ b1g,
    const float* __restrict__ rgbwg, const float* __restrict__ rgbbg,
    float* __restrict__ density, float* __restrict__ out_rgb)
{
    extern __shared__ char smem[];
    const uint32_t sb = smem_u32(smem);
    float* bias = (float*)(smem + SB_BIAS);
    __half* FEh = (__half*)(smem + FE_OFF);   // [128][56]
    __half* Hh  = (__half*)(smem + H_OFF);    // [128][72]
    __half* U1h = (__half*)(smem + U1_OFF);   // [64][56]
    __half* U2h = (__half*)(smem + U2_OFF);   // [256][72]
    __nv_bfloat16* Xp = (__nv_bfloat16*)(smem + SB_X);     // [128][264]
    __nv_bfloat16* Bp = (__nv_bfloat16*)(smem + SB_BOTT);  // [128][296]

    const int t = threadIdx.x;
    const int wid = t >> 5, lane = t & 31;
    const int g = lane >> 2, tq = lane & 3;
    const size_t base = (size_t)blockIdx.x * TILE_M;

    // ---- phase 0: small data + pads ----
    if (t < 64)  bias[BI_SB1 + t] = sb1g[t];
    if (t >= 64 && t < 320) bias[BI_SB2 + t - 64] = sb2g[t - 64];
    if (t < 256) { bias[BI_B0 + t] = b0g[t]; bias[BI_B1 + t] = b1g[t]; }
    for (int i = t; i < 768; i += 512) bias[BI_RW + i] = rgbwg[i];
    if (t < 3) bias[BI_RB + t] = rgbbg[t];
    if (t < 64) {
        int ray = (int)(base >> 6) + (t >> 5);
        int i = t & 31;
        float v = 0.0f;
        if (i < 27) {
            float dx = viewdirs[ray * 3 + 0];
            float dy = viewdirs[ray * 3 + 1];
            float dz = viewdirs[ray * 3 + 2];
            if (i < 3) v = (i == 0) ? dx : ((i == 1) ? dy : dz);
            else {
                int j = i - 3, deg = j / 6, rem = j % 6;
                float d = ((rem % 3) == 0) ? dx : (((rem % 3) == 1) ? dy : dz);
                float xb = d * (float)(1 << deg);
                v = (rem < 3) ? sinf(xb) : sinf(xb + 1.5707964f);
            }
        }
        bias[BI_DE + (t >> 5) * 32 + i] = v;
    }
    if (t < 128) STS_ZERO16(sb + FE_OFF + (uint32_t)(t * 112 + 80));

    // ---- phase 0: cp.async group G0 (feats, U1, U2 — all fp16) ----
    for (int i = t; i < 128 * 5; i += 512) {
        int r = i / 5, s = i % 5;
        CP16(sb + FE_OFF + (uint32_t)(r * 112 + s * 16),
             feats + (base + (size_t)r) * 40 + s * 8);
    }
    for (int i = t; i < 64 * 6; i += 512) {
        int r = i / 6, s = i % 6;
        CP16(sb + U1_OFF + (uint32_t)(r * 112 + s * 16), U1Tg + (size_t)r * 48 + s * 8);
    }
#pragma unroll
    for (int j = 0; j < 4; j++) {
        int i = t + 512 * j;
        int r = i >> 3, s = i & 7;
        CP16(sb + U2_OFF + (uint32_t)(r * 144 + s * 16), U2Tg + (size_t)r * 64 + s * 8);
    }
    CPCOMMIT();

    auto issueW = [&](int p) {
        const uint32_t wbase = sb + SB_W + (uint32_t)(p & 3) * WBUF_B;
        const __nv_bfloat16* wsrc; int wld, wcol;
        if (p < 9)       { wsrc = W0T; wld = 288; wcol = p * 32; }
        else if (p < 17) { wsrc = W1T; wld = 544; wcol = (p - 9) * 32; }
        else             { wsrc = W1T; wld = 544; wcol = 256 + (p - 17) * 32; }
#pragma unroll
        for (int j = 0; j < 2; j++) {
            int i = t + 512 * j, row = i >> 2, seg = i & 3;
            CP16(wbase + (uint32_t)row * 80u + (uint32_t)seg * 16u,
                 wsrc + (size_t)row * wld + wcol + seg * 8);
        }
    };
    issueW(0); CPCOMMIT();
    issueW(1); CPCOMMIT();
    issueW(2); CPCOMMIT();

    CPWAIT3();
    __syncthreads();

    // ---- phase 1: GEMM0a (fp16): h = relu(feats @ U1 + sb1), K=48, N=64 ----
    {
        const int m0a = (wid & 3) * 32, n0a = (wid >> 2) * 16;
        float acc0[2][2][4];
#pragma unroll
        for (int mf = 0; mf < 2; mf++)
#pragma unroll
            for (int nf = 0; nf < 2; nf++) {
                int col = n0a + nf * 8 + tq * 2;
                acc0[mf][nf][0] = bias[BI_SB1 + col];
                acc0[mf][nf][1] = bias[BI_SB1 + col + 1];
                acc0[mf][nf][2] = bias[BI_SB1 + col];
                acc0[mf][nf][3] = bias[BI_SB1 + col + 1];
            }
#pragma unroll
        for (int ks = 0; ks < 3; ks++) {
            const int kk = ks * 16;
            uint32_t a[2][4], b[2][2];
#pragma unroll
            for (int mf = 0; mf < 2; mf++) {
                const __half* ap = FEh + (m0a + mf * 16 + g) * 56 + kk + tq * 2;
                a[mf][0] = *(const uint32_t*)ap;
                a[mf][1] = *(const uint32_t*)(ap + 8 * 56);
                a[mf][2] = *(const uint32_t*)(ap + 8);
                a[mf][3] = *(const uint32_t*)(ap + 8 * 56 + 8);
            }
#pragma unroll
            for (int nf = 0; nf < 2; nf++) {
                const __half* bp = U1h + (n0a + nf * 8 + g) * 56 + kk + tq * 2;
                b[nf][0] = *(const uint32_t*)bp;
                b[nf][1] = *(const uint32_t*)(bp + 8);
            }
#pragma unroll
            for (int mf = 0; mf < 2; mf++)
#pragma unroll
                for (int nf = 0; nf < 2; nf++)
                    mma_f16(acc0[mf][nf], a[mf][0], a[mf][1], a[mf][2], a[mf][3],
                            b[nf][0], b[nf][1]);
        }
        __syncthreads();
#pragma unroll
        for (int mf = 0; mf < 2; mf++) {
            const int r0 = m0a + mf * 16 + g;
#pragma unroll
            for (int nf = 0; nf < 2; nf++) {
                const int col = n0a + nf * 8 + tq * 2;
                *(uint32_t*)(Hh + r0 * 72 + col) =
                    h16pack(fmaxf(acc0[mf][nf][0], 0.0f), fmaxf(acc0[mf][nf][1], 0.0f));
                *(uint32_t*)(Hh + (r0 + 8) * 72 + col) =
                    h16pack(fmaxf(acc0[mf][nf][2], 0.0f), fmaxf(acc0[mf][nf][3], 0.0f));
            }
        }
    }
    __syncthreads();

    // ---- phase 2: GEMM0b (fp16): bott = h @ U2 + sb2 -> BOTT bf16 ----
    const int wm = wid & 1, wn = wid >> 1;
    const int m0 = wm * 64, n0 = wn * 32;
    float acc[4][4][4];
#pragma unroll
    for (int mf = 0; mf < 4; mf++)
#pragma unroll
        for (int nf = 0; nf < 4; nf++) {
            int col = n0 + nf * 8 + tq * 2;
            acc[mf][nf][0] = bias[BI_SB2 + col];
            acc[mf][nf][1] = bias[BI_SB2 + col + 1];
            acc[mf][nf][2] = bias[BI_SB2 + col];
            acc[mf][nf][3] = bias[BI_SB2 + col + 1];
        }
#pragma unroll
    for (int ks = 0; ks < 4; ks++) {
        const int kk = ks * 16;
        uint32_t a[4][4], b[4][2];
#pragma unroll
        for (int mf = 0; mf < 4; mf++) {
            const __half* ap = Hh + (m0 + mf * 16 + g) * 72 + kk + tq * 2;
            a[mf][0] = *(const uint32_t*)ap;
            a[mf][1] = *(const uint32_t*)(ap + 8 * 72);
            a[mf][2] = *(const uint32_t*)(ap + 8);
            a[mf][3] = *(const uint32_t*)(ap + 8 * 72 + 8);
        }
#pragma unroll
        for (int nf = 0; nf < 4; nf++) {
            const __half* bp = U2h + (n0 + nf * 8 + g) * 72 + kk + tq * 2;
            b[nf][0] = *(const uint32_t*)bp;
            b[nf][1] = *(const uint32_t*)(bp + 8);
        }
#pragma unroll
        for (int mf = 0; mf < 4; mf++)
#pragma unroll
            for (int nf = 0; nf < 4; nf++)
                mma_f16(acc[mf][nf], a[mf][0], a[mf][1], a[mf][2], a[mf][3],
                        b[nf][0], b[nf][1]);
    }
    __syncthreads();

    // epilogue 0b: BOTT bf16 cols 0..255 + density; direnc cols 256..287
#pragma unroll
    for (int mf = 0; mf < 4; mf++) {
        const int r0 = m0 + mf * 16 + g;
#pragma unroll
        for (int nf = 0; nf < 4; nf++) {
            const int col = n0 + nf * 8 + tq * 2;
            *(uint32_t*)(Bp + r0 * BSTRIDE + col)       = bf16pack(acc[mf][nf][0], acc[mf][nf][1]);
            *(uint32_t*)(Bp + (r0 + 8) * BSTRIDE + col) = bf16pack(acc[mf][nf][2], acc[mf][nf][3]);
        }
        if (wn == 0 && tq == 0) {
            float r = acc[mf][0][0] - 1.0f;
            density[base + r0] = (r > 0.0f) ? (r + log1pf(expf(-r))) : log1pf(expf(r));
            r = acc[mf][0][2] - 1.0f;
            density[base + r0 + 8] = (r > 0.0f) ? (r + log1pf(expf(-r))) : log1pf(expf(r));
        }
    }
#pragma unroll
    for (int j = 0; j < 4; j++) {
        int i = t + 512 * j;
        int row = i >> 4, q = i & 15;
        const float* de = &bias[BI_DE + (row >> 6) * 32];
        *(uint32_t*)(Bp + row * BSTRIDE + 256 + q * 2) = bf16pack(de[q * 2], de[q * 2 + 1]);
    }

    // re-init acc with b0 for GEMM1
#pragma unroll
    for (int mf = 0; mf < 4; mf++)
#pragma unroll
        for (int nf = 0; nf < 4; nf++) {
            int col = n0 + nf * 8 + tq * 2;
            acc[mf][nf][0] = bias[BI_B0 + col];
            acc[mf][nf][1] = bias[BI_B0 + col + 1];
            acc[mf][nf][2] = bias[BI_B0 + col];
            acc[mf][nf][3] = bias[BI_B0 + col + 1];
        }

    // ---- phase 3: main loop, 26 chunks; precomputed LDSM base addresses ----
    const int arow = lane & 15;
    const int ak8  = ((lane >> 4) & 1) << 3;
    const int brow = ((lane >> 1) & 8) + (lane & 7);
    const int bk8  = lane & 8;

    uint32_t aRowB[4], aRowX[4];
#pragma unroll
    for (int mf = 0; mf < 4; mf++) {
        aRowB[mf] = sb + SB_BOTT +
            (uint32_t)(((m0 + mf * 16 + arow) * BSTRIDE + ak8) * 2);
        aRowX[mf] = sb + SB_X +
            (uint32_t)(((m0 + mf * 16 + arow) * XSTRIDE + ak8) * 2);
    }
    const uint32_t wRow0 = (uint32_t)(((n0 + brow) * 40 + bk8) * 2);
    const uint32_t wRow1 = (uint32_t)(((n0 + 16 + brow) * 40 + bk8) * 2);

    for (int c = 0; c < NCHUNK; c++) {
        if (c <= NCHUNK - 3)      { CPWAIT2(); }
        else if (c == NCHUNK - 2) { CPWAIT1(); }
        else                      { CPWAIT0(); }
        __syncthreads();

        const bool isX = (c >= 9 && c < 17);
        const int k0 = (c < 9) ? c * 32 : ((c < 17) ? (c - 9) * 32 : (c - 17) * 32);
        const uint32_t kB = (uint32_t)(k0 * 2);
        const uint32_t wPane = sb + SB_W + (uint32_t)(c & 3) * WBUF_B;

#pragma unroll
        for (int ks = 0; ks < 2; ks++) {
            const uint32_t kOff = kB + (uint32_t)(ks * 32);
            uint32_t a[4][4], bb[2][4];
#pragma unroll
            for (int mf = 0; mf < 4; mf++)
                LDSM4(a[mf], (isX ? aRowX[mf] : aRowB[mf]) + kOff);
            LDSM4(bb[0], wPane + wRow0 + (uint32_t)(ks * 32));
            LDSM4(bb[1], wPane + wRow1 + (uint32_t)(ks * 32));
#pragma unroll
            for (int mf = 0; mf < 4; mf++)
#pragma unroll
                for (int p = 0; p < 2; p++) {
                    mma_bf16(acc[mf][p * 2 + 0], a[mf][0], a[mf][1], a[mf][2], a[mf][3],
                             bb[p][0], bb[p][1]);
                    mma_bf16(acc[mf][p * 2 + 1], a[mf][0], a[mf][1], a[mf][2], a[mf][3],
                             bb[p][2], bb[p][3]);
                }
        }

        if (c == 8) {
            // epilogue 1: relu(x + b0) -> bf16 -> X panel; reset acc to b1.
#pragma unroll
            for (int mf = 0; mf < 4; mf++) {
                const int r0 = m0 + mf * 16 + g;
#pragma unroll
                for (int nf = 0; nf < 4; nf++) {
                    const int col = n0 + nf * 8 + tq * 2;
                    *(uint32_t*)(Xp + r0 * XSTRIDE + col) =
                        bf16pack(fmaxf(acc[mf][nf][0], 0.0f), fmaxf(acc[mf][nf][1], 0.0f));
                    *(uint32_t*)(Xp + (r0 + 8) * XSTRIDE + col) =
                        bf16pack(fmaxf(acc[mf][nf][2], 0.0f), fmaxf(acc[mf][nf][3], 0.0f));
                    acc[mf][nf][0] = bias[BI_B1 + col];
                    acc[mf][nf][1] = bias[BI_B1 + col + 1];
                    acc[mf][nf][2] = bias[BI_B1 + col];
                    acc[mf][nf][3] = bias[BI_B1 + col + 1];
                }
            }
        }
        if (c + 3 < NCHUNK) issueW(c + 3);
        CPCOMMIT();
    }

    // ---- phase 4: rgb head ----
    float p[8][3];
#pragma unroll
    for (int r = 0; r < 8; r++) { p[r][0] = 0; p[r][1] = 0; p[r][2] = 0; }
#pragma unroll
    for (int mf = 0; mf < 4; mf++)
#pragma unroll
        for (int nf = 0; nf < 4; nf++) {
            const int col0 = n0 + nf * 8 + tq * 2, col1 = col0 + 1;
            float y00 = fmaxf(acc[mf][nf][0], 0.0f);
            float y01 = fmaxf(acc[mf][nf][1], 0.0f);
            float y10 = fmaxf(acc[mf][nf][2], 0.0f);
            float y11 = fmaxf(acc[mf][nf][3], 0.0f);
#pragma unroll
            for (int ch = 0; ch < 3; ch++) {
                float w0 = bias[BI_RW + col0 * 3 + ch], w1 = bias[BI_RW + col1 * 3 + ch];
                p[mf * 2 + 0][ch] += y00 * w0 + y01 * w1;
                p[mf * 2 + 1][ch] += y10 * w0 + y11 * w1;
            }
        }
#pragma unroll
    for (int r = 0; r < 8; r++)
#pragma unroll
        for (int ch = 0; ch < 3; ch++) {
            p[r][ch] += __shfl_xor_sync(0xffffffffu, p[r][ch], 1);
            p[r][ch] += __shfl_xor_sync(0xffffffffu, p[r][ch], 2);
        }

    float* part = (float*)(smem + SB_BOTT);
    __syncthreads();
    if (tq == 0) {
#pragma unroll
        for (int mf = 0; mf < 4; mf++)
#pragma unroll
            for (int h = 0; h < 2; h++) {
                int row = m0 + mf * 16 + g + 8 * h;
                int r = mf * 2 + h;
                part[(wn * 128 + row) * 3 + 0] = p[r][0];
                part[(wn * 128 + row) * 3 + 1] = p[r][1];
                part[(wn * 128 + row) * 3 + 2] = p[r][2];
            }
    }
    __syncthreads();
    if (t < 384) {
        const int m = t / 3, ch = t - m * 3;
        float v = bias[BI_RB + ch];
#pragma unroll
        for (int gq = 0; gq < 8; gq++) v += part[(gq * 128 + m) * 3 + ch];
        float sg = 1.0f / (1.0f + expf(-v));
        out_rgb[(base + (size_t)m) * 3 + ch] = sg * 1.002f - 0.001f;
    }
}

// ---------------------------------------------------------------- launch
extern "C" void kernel_launch(void* const* d_in, const int* in_sizes, int n_in,
                              void* d_out, int out_size)
{
    const float*  coords   = (const float*)d_in[0];
    const float*  viewdirs = (const float*)d_in[2];
    const float4* emb      = (const float4*)d_in[3];
    const float*  w1       = (const float*)d_in[4];
    const float*  b1       = (const float*)d_in[5];
    const float*  w2       = (const float*)d_in[6];
    const float*  b2       = (const float*)d_in[7];
    const float*  lin0_w   = (const float*)d_in[8];
    const float*  lin0_b   = (const float*)d_in[9];
    const float*  lin1_w   = (const float*)d_in[10];
    const float*  lin1_b   = (const float*)d_in[11];
    const float*  rgb_w    = (const float*)d_in[12];
    const float*  rgb_b    = (const float*)d_in[13];

    float* dout    = (float*)d_out;
    float* density = dout;
    float* rgb     = dout + NPTS;

    __half *feats, *U1T, *U2T;
    __nv_bfloat16 *W0T, *W1T;
    cudaGetSymbolAddress((void**)&feats, g_feats);
    cudaGetSymbolAddress((void**)&W0T, g_W0T);
    cudaGetSymbolAddress((void**)&W1T, g_W1T);
    cudaGetSymbolAddress((void**)&U1T, g_U1T);
    cudaGetSymbolAddress((void**)&U2T, g_U2T);

    cudaFuncSetAttribute(kernF, cudaFuncAttributeMaxDynamicSharedMemorySize,
                         SMEMF_BYTES);

    prepW<<<544, 256>>>(lin0_w, lin1_w, w1, w2, W0T, W1T, U1T, U2T);
    kernA<<<NPTS / 128, 256>>>(coords, emb, feats);
    kernF<<<NTILES, 512, SMEMF_BYTES>>>(feats, viewdirs, U1T, U2T, b1, b2,
                                        W0T, W1T, lin0_b, lin1_b,
                                        rgb_w, rgb_b, density, rgb);
}

// round 17
// speedup vs baseline: 1.0973x; 1.0319x over previous
#include <cuda_runtime.h>
#include <cuda_bf16.h>
#include <cuda_fp16.h>
#include <math.h>
#include <stdint.h>

// ---------------------------------------------------------------- constants
#define NPTS (4096 * 64)
#define NRAYS 4096
#define HASH_MASK 2097151u
#define P1H 2654435761u
#define P2H 805459861u

#define TILE_M 128
#define NTILES (NPTS / TILE_M)   // 2048
#define NCHUNK 26                 // 9 (gemm1) + 8 (gemm2 X) + 9 (gemm2 bott)

// ---------------- fused kernel smem layout (bytes) ----------------
#define XSTRIDE 264
#define BSTRIDE 296
#define SB_X    0
#define U2_OFF  0
#define SB_BOTT 67584
#define FE_OFF  67584
#define H_OFF   81920
#define U1_OFF  100352
#define SB_W    143360
#define WBUF_B  20480
#define SB_BIAS 225280
#define SMEMF_BYTES (SB_BIAS + 6672)    // 231952

#define BI_SB1  0
#define BI_SB2  64
#define BI_B0   320
#define BI_B1   576
#define BI_RW   832
#define BI_RB   1600
#define BI_DE   1604

// ---------------------------------------------------------------- globals
__device__ __half g_feats[(size_t)NPTS * 40];
__device__ __nv_bfloat16 g_W0T[256 * 288];
__device__ __nv_bfloat16 g_W1T[256 * 544];
__device__ __half g_U1T[64 * 48];
__device__ __half g_U2T[256 * 64];
__constant__ int c_offs[10] = {0, 4096, 36864, 299008, 2396160,
                               4493312, 6590464, 8687616, 10784768, 12881920};

// ---------------------------------------------------------------- helpers
__device__ __forceinline__ uint32_t bf16pack(float lo, float hi) {
    uint32_t d;
    asm("cvt.rn.bf16x2.f32 %0, %1, %2;" : "=r"(d) : "f"(hi), "f"(lo));
    return d;
}
__device__ __forceinline__ uint32_t h16pack(float lo, float hi) {
    uint32_t d;
    asm("cvt.rn.f16x2.f32 %0, %1, %2;" : "=r"(d) : "f"(hi), "f"(lo));
    return d;
}
__device__ __forceinline__ void mma_f16(float c[4],
    uint32_t a0, uint32_t a1, uint32_t a2, uint32_t a3,
    uint32_t b0, uint32_t b1)
{
    asm volatile(
        "mma.sync.aligned.m16n8k16.row.col.f32.f16.f16.f32 "
        "{%0,%1,%2,%3},{%4,%5,%6,%7},{%8,%9},{%0,%1,%2,%3};"
        : "+f"(c[0]), "+f"(c[1]), "+f"(c[2]), "+f"(c[3])
        : "r"(a0), "r"(a1), "r"(a2), "r"(a3), "r"(b0), "r"(b1));
}
__device__ __forceinline__ void mma_bf16(float c[4],
    uint32_t a0, uint32_t a1, uint32_t a2, uint32_t a3,
    uint32_t b0, uint32_t b1)
{
    asm volatile(
        "mma.sync.aligned.m16n8k16.row.col.f32.bf16.bf16.f32 "
        "{%0,%1,%2,%3},{%4,%5,%6,%7},{%8,%9},{%0,%1,%2,%3};"
        : "+f"(c[0]), "+f"(c[1]), "+f"(c[2]), "+f"(c[3])
        : "r"(a0), "r"(a1), "r"(a2), "r"(a3), "r"(b0), "r"(b1));
}
#define LDSM4(r, a) \
    asm volatile("ldmatrix.sync.aligned.m8n8.x4.shared.b16 {%0,%1,%2,%3}, [%4];" \
        : "=r"((r)[0]), "=r"((r)[1]), "=r"((r)[2]), "=r"((r)[3]) : "r"(a))
__device__ __forceinline__ uint32_t smem_u32(const void* p) {
    uint32_t a;
    asm("{ .reg .u64 t; cvta.to.shared.u64 t, %1; cvt.u32.u64 %0, t; }"
        : "=r"(a) : "l"(p));
    return a;
}
#define CP16(d, s) asm volatile("cp.async.cg.shared.global [%0], [%1], 16;" :: "r"(d), "l"(s))
#define CPCOMMIT() asm volatile("cp.async.commit_group;")
#define CPWAIT3()  asm volatile("cp.async.wait_group 3;" ::: "memory")
#define CPWAIT2()  asm volatile("cp.async.wait_group 2;" ::: "memory")
#define CPWAIT1()  asm volatile("cp.async.wait_group 1;" ::: "memory")
#define CPWAIT0()  asm volatile("cp.async.wait_group 0;" ::: "memory")
#define STS_ZERO16(a) asm volatile("st.shared.v4.u32 [%0], {%1,%1,%1,%1};" :: "r"(a), "r"(0u) : "memory")

// ---------------------------------------------------------------- prepW
__global__ void __launch_bounds__(256) prepW(
    const float* __restrict__ l0, const float* __restrict__ l1,
    const float* __restrict__ w1, const float* __restrict__ w2,
    __nv_bfloat16* __restrict__ W0T, __nv_bfloat16* __restrict__ W1T,
    __half* __restrict__ U1T, __half* __restrict__ U2T)
{
    int idx = blockIdx.x * 256 + threadIdx.x;
    if (idx < 256 * 288) {
        int n = idx / 288, k = idx % 288;
        W0T[idx] = __float2bfloat16((k < 283) ? l0[k * 256 + n] : 0.0f);
    }
    if (idx < 256 * 544) {
        int n = idx / 544, k = idx % 544;
        W1T[idx] = __float2bfloat16((k < 539) ? l1[k * 256 + n] : 0.0f);
    }
    if (idx < 64 * 48) {
        int n = idx / 48, k = idx % 48;
        U1T[idx] = __float2half((k < 40) ? w1[k * 64 + n] : 0.0f);
    }
    if (idx < 256 * 64) {
        int n = idx / 64, k = idx % 64;
        U2T[idx] = __float2half(w2[k * 256 + n]);
    }
}

// ---------------------------------------------------------------- kernel A
// gather only; 2 threads per point (5 levels each); fp16 output
__global__ void __launch_bounds__(256) kernA(
    const float* __restrict__ coords,
    const float4* __restrict__ emb,
    __half* __restrict__ feats)
{
    const int t = threadIdx.x;
    const int pid = blockIdx.x * 128 + (t & 127);
    const int half_ = t >> 7;   // 0: levels 0-4, 1: levels 5-9

    float cx = coords[pid * 3 + 0];
    float cy = coords[pid * 3 + 1];
    float cz = coords[pid * 3 + 2];
    float nn = sqrtf(cx * cx + cy * cy + cz * cz);
    nn = fmaxf(nn, 1.1920929e-7f);
    if (nn > 1.0f) {
        float sc = 2.0f - 1.0f / nn;
        cx = sc * (cx / nn); cy = sc * (cy / nn); cz = sc * (cz / nn);
    }
    const float ux = (cx * 0.5f + 1.0f) * 0.5f;
    const float uy = (cy * 0.5f + 1.0f) * 0.5f;
    const float uz = (cz * 0.5f + 1.0f) * 0.5f;

    const int l0 = half_ * 5;
    uint2* out = (uint2*)(feats + (size_t)pid * 40 + l0 * 4);

#pragma unroll
    for (int li = 0; li < 5; li++) {
        const int l = l0 + li;
        const int res = 16 << l;
        const float s = (float)res - 1.0f;
        float px = ux * s + 0.5f, py = uy * s + 0.5f, pz = uz * s + 0.5f;
        float gxf = floorf(px), gyf = floorf(py), gzf = floorf(pz);
        float fx = px - gxf, fy = py - gyf, fz = pz - gzf;
        int gx = (int)gxf, gy = (int)gyf, gz = (int)gzf;
        float f0 = 0, f1 = 0, f2 = 0, f3 = 0;
        const int off = c_offs[l];
        const bool dense = (l < 4);
#pragma unroll
        for (int c = 0; c < 8; c++) {
            const int b0 = c & 1, b1c = (c >> 1) & 1, b2c = (c >> 2) & 1;
            float w = (b0 ? fx : 1.0f - fx) * (b1c ? fy : 1.0f - fy)
                    * (b2c ? fz : 1.0f - fz);
            int idx;
            if (dense) {
                idx = (gx + b0) + (gy + b1c) * res + (gz + b2c) * res * res;
            } else {
                idx = (int)(((uint32_t)(gx + b0)
                           ^ ((uint32_t)(gy + b1c) * P1H)
                           ^ ((uint32_t)(gz + b2c) * P2H)) & HASH_MASK);
            }
            float4 e = __ldg(&emb[off + idx]);
            f0 += w * e.x; f1 += w * e.y; f2 += w * e.z; f3 += w * e.w;
        }
        out[li] = make_uint2(h16pack(f0, f1), h16pack(f2, f3));
    }
}

// ---------------------------------------------------------------- fused kernel
__global__ void __launch_bounds__(512, 1) kernF(
    const __half* __restrict__ feats,
    const float* __restrict__ viewdirs,
    const __half* __restrict__ U1Tg, const __half* __restrict__ U2Tg,
    const float* __restrict__ sb1g, const float* __restrict__ sb2g,
    const __nv_bfloat16* __restrict__ W0T, const __nv_bfloat16* __restrict__ W1T,
    const float* __restrict__ b0g, const float* __restrict__ b1g,
    const float* __restrict__ rgbwg, const float* __restrict__ rgbbg,
    float* __restrict__ density, float* __restrict__ out_rgb)
{
    extern __shared__ char smem[];
    const uint32_t sb = smem_u32(smem);
    float* bias = (float*)(smem + SB_BIAS);
    __half* FEh = (__half*)(smem + FE_OFF);   // [128][56]
    __half* Hh  = (__half*)(smem + H_OFF);    // [128][72]
    __half* U1h = (__half*)(smem + U1_OFF);   // [64][56]
    __half* U2h = (__half*)(smem + U2_OFF);   // [256][72]
    __nv_bfloat16* Xp = (__nv_bfloat16*)(smem + SB_X);     // [128][264]
    __nv_bfloat16* Bp = (__nv_bfloat16*)(smem + SB_BOTT);  // [128][296]

    const int t = threadIdx.x;
    const int wid = t >> 5, lane = t & 31;
    const int g = lane >> 2, tq = lane & 3;
    const size_t base = (size_t)blockIdx.x * TILE_M;

    // ---- phase 0: small data + pads ----
    if (t < 64)  bias[BI_SB1 + t] = sb1g[t];
    if (t >= 64 && t < 320) bias[BI_SB2 + t - 64] = sb2g[t - 64];
    if (t < 256) { bias[BI_B0 + t] = b0g[t]; bias[BI_B1 + t] = b1g[t]; }
    for (int i = t; i < 768; i += 512) bias[BI_RW + i] = rgbwg[i];
    if (t < 3) bias[BI_RB + t] = rgbbg[t];
    if (t < 64) {
        int ray = (int)(base >> 6) + (t >> 5);
        int i = t & 31;
        float v = 0.0f;
        if (i < 27) {
            float dx = viewdirs[ray * 3 + 0];
            float dy = viewdirs[ray * 3 + 1];
            float dz = viewdirs[ray * 3 + 2];
            if (i < 3) v = (i == 0) ? dx : ((i == 1) ? dy : dz);
            else {
                int j = i - 3, deg = j / 6, rem = j % 6;
                float d = ((rem % 3) == 0) ? dx : (((rem % 3) == 1) ? dy : dz);
                float xb = d * (float)(1 << deg);
                v = (rem < 3) ? sinf(xb) : sinf(xb + 1.5707964f);
            }
        }
        bias[BI_DE + (t >> 5) * 32 + i] = v;
    }
    if (t < 128) STS_ZERO16(sb + FE_OFF + (uint32_t)(t * 112 + 80));

    // ---- phase 0: cp.async group G0 (feats, U1, U2 — all fp16) ----
    for (int i = t; i < 128 * 5; i += 512) {
        int r = i / 5, s = i % 5;
        CP16(sb + FE_OFF + (uint32_t)(r * 112 + s * 16),
             feats + (base + (size_t)r) * 40 + s * 8);
    }
    for (int i = t; i < 64 * 6; i += 512) {
        int r = i / 6, s = i % 6;
        CP16(sb + U1_OFF + (uint32_t)(r * 112 + s * 16), U1Tg + (size_t)r * 48 + s * 8);
    }
#pragma unroll
    for (int j = 0; j < 4; j++) {
        int i = t + 512 * j;
        int r = i >> 3, s = i & 7;
        CP16(sb + U2_OFF + (uint32_t)(r * 144 + s * 16), U2Tg + (size_t)r * 64 + s * 8);
    }
    CPCOMMIT();

    // ---- issueW with precomputed per-thread addressing ----
    // rows/segs are t-invariant: row0 = t>>2, row1 = row0+128; seg = t&3
    const int wRowA = t >> 2, wSeg = t & 3;
    const uint32_t wDst0 = (uint32_t)(wRowA * 80 + wSeg * 16);
    const uint32_t wDst1 = (uint32_t)((wRowA + 128) * 80 + wSeg * 16);
    const __nv_bfloat16* w0Src0 = W0T + (size_t)wRowA * 288 + wSeg * 8;
    const __nv_bfloat16* w0Src1 = W0T + (size_t)(wRowA + 128) * 288 + wSeg * 8;
    const __nv_bfloat16* w1Src0 = W1T + (size_t)wRowA * 544 + wSeg * 8;
    const __nv_bfloat16* w1Src1 = W1T + (size_t)(wRowA + 128) * 544 + wSeg * 8;

    auto issueW = [&](int p) {
        const uint32_t wbase = sb + SB_W + (uint32_t)(p & 3) * WBUF_B;
        const __nv_bfloat16 *s0, *s1;
        if (p < 9)       { int wc = p * 32;              s0 = w0Src0 + wc; s1 = w0Src1 + wc; }
        else if (p < 17) { int wc = (p - 9) * 32;        s0 = w1Src0 + wc; s1 = w1Src1 + wc; }
        else             { int wc = 256 + (p - 17) * 32; s0 = w1Src0 + wc; s1 = w1Src1 + wc; }
        CP16(wbase + wDst0, s0);
        CP16(wbase + wDst1, s1);
    };
    issueW(0); CPCOMMIT();
    issueW(1); CPCOMMIT();
    issueW(2); CPCOMMIT();

    CPWAIT3();
    __syncthreads();

    // ---- phase 1: GEMM0a (fp16): h = relu(feats @ U1 + sb1), K=48, N=64 ----
    {
        const int m0a = (wid & 3) * 32, n0a = (wid >> 2) * 16;
        float acc0[2][2][4];
#pragma unroll
        for (int mf = 0; mf < 2; mf++)
#pragma unroll
            for (int nf = 0; nf < 2; nf++) {
                int col = n0a + nf * 8 + tq * 2;
                acc0[mf][nf][0] = bias[BI_SB1 + col];
                acc0[mf][nf][1] = bias[BI_SB1 + col + 1];
                acc0[mf][nf][2] = bias[BI_SB1 + col];
                acc0[mf][nf][3] = bias[BI_SB1 + col + 1];
            }
#pragma unroll
        for (int ks = 0; ks < 3; ks++) {
            const int kk = ks * 16;
            uint32_t a[2][4], b[2][2];
#pragma unroll
            for (int mf = 0; mf < 2; mf++) {
                const __half* ap = FEh + (m0a + mf * 16 + g) * 56 + kk + tq * 2;
                a[mf][0] = *(const uint32_t*)ap;
                a[mf][1] = *(const uint32_t*)(ap + 8 * 56);
                a[mf][2] = *(const uint32_t*)(ap + 8);
                a[mf][3] = *(const uint32_t*)(ap + 8 * 56 + 8);
            }
#pragma unroll
            for (int nf = 0; nf < 2; nf++) {
                const __half* bp = U1h + (n0a + nf * 8 + g) * 56 + kk + tq * 2;
                b[nf][0] = *(const uint32_t*)bp;
                b[nf][1] = *(const uint32_t*)(bp + 8);
            }
#pragma unroll
            for (int mf = 0; mf < 2; mf++)
#pragma unroll
                for (int nf = 0; nf < 2; nf++)
                    mma_f16(acc0[mf][nf], a[mf][0], a[mf][1], a[mf][2], a[mf][3],
                            b[nf][0], b[nf][1]);
        }
        __syncthreads();
#pragma unroll
        for (int mf = 0; mf < 2; mf++) {
            const int r0 = m0a + mf * 16 + g;
#pragma unroll
            for (int nf = 0; nf < 2; nf++) {
                const int col = n0a + nf * 8 + tq * 2;
                *(uint32_t*)(Hh + r0 * 72 + col) =
                    h16pack(fmaxf(acc0[mf][nf][0], 0.0f), fmaxf(acc0[mf][nf][1], 0.0f));
                *(uint32_t*)(Hh + (r0 + 8) * 72 + col) =
                    h16pack(fmaxf(acc0[mf][nf][2], 0.0f), fmaxf(acc0[mf][nf][3], 0.0f));
            }
        }
    }
    __syncthreads();

    // ---- phase 2: GEMM0b (fp16): bott = h @ U2 + sb2 -> BOTT bf16 ----
    const int wm = wid & 1, wn = wid >> 1;
    const int m0 = wm * 64, n0 = wn * 32;
    float acc[4][4][4];
#pragma unroll
    for (int mf = 0; mf < 4; mf++)
#pragma unroll
        for (int nf = 0; nf < 4; nf++) {
            int col = n0 + nf * 8 + tq * 2;
            acc[mf][nf][0] = bias[BI_SB2 + col];
            acc[mf][nf][1] = bias[BI_SB2 + col + 1];
            acc[mf][nf][2] = bias[BI_SB2 + col];
            acc[mf][nf][3] = bias[BI_SB2 + col + 1];
        }
#pragma unroll
    for (int ks = 0; ks < 4; ks++) {
        const int kk = ks * 16;
        uint32_t a[4][4], b[4][2];
#pragma unroll
        for (int mf = 0; mf < 4; mf++) {
            const __half* ap = Hh + (m0 + mf * 16 + g) * 72 + kk + tq * 2;
            a[mf][0] = *(const uint32_t*)ap;
            a[mf][1] = *(const uint32_t*)(ap + 8 * 72);
            a[mf][2] = *(const uint32_t*)(ap + 8);
            a[mf][3] = *(const uint32_t*)(ap + 8 * 72 + 8);
        }
#pragma unroll
        for (int nf = 0; nf < 4; nf++) {
            const __half* bp = U2h + (n0 + nf * 8 + g) * 72 + kk + tq * 2;
            b[nf][0] = *(const uint32_t*)bp;
            b[nf][1] = *(const uint32_t*)(bp + 8);
        }
#pragma unroll
        for (int mf = 0; mf < 4; mf++)
#pragma unroll
            for (int nf = 0; nf < 4; nf++)
                mma_f16(acc[mf][nf], a[mf][0], a[mf][1], a[mf][2], a[mf][3],
                        b[nf][0], b[nf][1]);
    }
    __syncthreads();

    // epilogue 0b: BOTT bf16 cols 0..255 + density; direnc cols 256..287
#pragma unroll
    for (int mf = 0; mf < 4; mf++) {
        const int r0 = m0 + mf * 16 + g;
#pragma unroll
        for (int nf = 0; nf < 4; nf++) {
            const int col = n0 + nf * 8 + tq * 2;
            *(uint32_t*)(Bp + r0 * BSTRIDE + col)       = bf16pack(acc[mf][nf][0], acc[mf][nf][1]);
            *(uint32_t*)(Bp + (r0 + 8) * BSTRIDE + col) = bf16pack(acc[mf][nf][2], acc[mf][nf][3]);
        }
        if (wn == 0 && tq == 0) {
            float r = acc[mf][0][0] - 1.0f;
            density[base + r0] = (r > 0.0f) ? (r + log1pf(expf(-r))) : log1pf(expf(r));
            r = acc[mf][0][2] - 1.0f;
            density[base + r0 + 8] = (r > 0.0f) ? (r + log1pf(expf(-r))) : log1pf(expf(r));
        }
    }
#pragma unroll
    for (int j = 0; j < 4; j++) {
        int i = t + 512 * j;
        int row = i >> 4, q = i & 15;
        const float* de = &bias[BI_DE + (row >> 6) * 32];
        *(uint32_t*)(Bp + row * BSTRIDE + 256 + q * 2) = bf16pack(de[q * 2], de[q * 2 + 1]);
    }

    // re-init acc with b0 for GEMM1
#pragma unroll
    for (int mf = 0; mf < 4; mf++)
#pragma unroll
        for (int nf = 0; nf < 4; nf++) {
            int col = n0 + nf * 8 + tq * 2;
            acc[mf][nf][0] = bias[BI_B0 + col];
            acc[mf][nf][1] = bias[BI_B0 + col + 1];
            acc[mf][nf][2] = bias[BI_B0 + col];
            acc[mf][nf][3] = bias[BI_B0 + col + 1];
        }

    // ---- phase 3: main loop, 26 chunks; precomputed LDSM base addresses ----
    const int arow = lane & 15;
    const int ak8  = ((lane >> 4) & 1) << 3;
    const int brow = ((lane >> 1) & 8) + (lane & 7);
    const int bk8  = lane & 8;

    uint32_t aRowB[4], aRowX[4];
#pragma unroll
    for (int mf = 0; mf < 4; mf++) {
        aRowB[mf] = sb + SB_BOTT +
            (uint32_t)(((m0 + mf * 16 + arow) * BSTRIDE + ak8) * 2);
        aRowX[mf] = sb + SB_X +
            (uint32_t)(((m0 + mf * 16 + arow) * XSTRIDE + ak8) * 2);
    }
    const uint32_t wRow0 = (uint32_t)(((n0 + brow) * 40 + bk8) * 2);
    const uint32_t wRow1 = (uint32_t)(((n0 + 16 + brow) * 40 + bk8) * 2);

    for (int c = 0; c < NCHUNK; c++) {
        if (c <= NCHUNK - 3)      { CPWAIT2(); }
        else if (c == NCHUNK - 2) { CPWAIT1(); }
        else                      { CPWAIT0(); }
        __syncthreads();

        const bool isX = (c >= 9 && c < 17);
        const int k0 = (c < 9) ? c * 32 : ((c < 17) ? (c - 9) * 32 : (c - 17) * 32);
        const uint32_t kB = (uint32_t)(k0 * 2);
        const uint32_t wPane = sb + SB_W + (uint32_t)(c & 3) * WBUF_B;

#pragma unroll
        for (int ks = 0; ks < 2; ks++) {
            const uint32_t kOff = kB + (uint32_t)(ks * 32);
            uint32_t a[4][4], bb[2][4];
#pragma unroll
            for (int mf = 0; mf < 4; mf++)
                LDSM4(a[mf], (isX ? aRowX[mf] : aRowB[mf]) + kOff);
            LDSM4(bb[0], wPane + wRow0 + (uint32_t)(ks * 32));
            LDSM4(bb[1], wPane + wRow1 + (uint32_t)(ks * 32));
#pragma unroll
            for (int mf = 0; mf < 4; mf++)
#pragma unroll
                for (int p = 0; p < 2; p++) {
                    mma_bf16(acc[mf][p * 2 + 0], a[mf][0], a[mf][1], a[mf][2], a[mf][3],
                             bb[p][0], bb[p][1]);
                    mma_bf16(acc[mf][p * 2 + 1], a[mf][0], a[mf][1], a[mf][2], a[mf][3],
                             bb[p][2], bb[p][3]);
                }
        }

        if (c == 8) {
            // epilogue 1: relu(x + b0) -> bf16 -> X panel; reset acc to b1.
#pragma unroll
            for (int mf = 0; mf < 4; mf++) {
                const int r0 = m0 + mf * 16 + g;
#pragma unroll
                for (int nf = 0; nf < 4; nf++) {
                    const int col = n0 + nf * 8 + tq * 2;
                    *(uint32_t*)(Xp + r0 * XSTRIDE + col) =
                        bf16pack(fmaxf(acc[mf][nf][0], 0.0f), fmaxf(acc[mf][nf][1], 0.0f));
                    *(uint32_t*)(Xp + (r0 + 8) * XSTRIDE + col) =
                        bf16pack(fmaxf(acc[mf][nf][2], 0.0f), fmaxf(acc[mf][nf][3], 0.0f));
                    acc[mf][nf][0] = bias[BI_B1 + col];
                    acc[mf][nf][1] = bias[BI_B1 + col + 1];
                    acc[mf][nf][2] = bias[BI_B1 + col];
                    acc[mf][nf][3] = bias[BI_B1 + col + 1];
                }
            }
        }
        if (c + 3 < NCHUNK) issueW(c + 3);
        CPCOMMIT();
    }

    // ---- phase 4: rgb head ----
    float p[8][3];
#pragma unroll
    for (int r = 0; r < 8; r++) { p[r][0] = 0; p[r][1] = 0; p[r][2] = 0; }
#pragma unroll
    for (int mf = 0; mf < 4; mf++)
#pragma unroll
        for (int nf = 0; nf < 4; nf++) {
            const int col0 = n0 + nf * 8 + tq * 2, col1 = col0 + 1;
            float y00 = fmaxf(acc[mf][nf][0], 0.0f);
            float y01 = fmaxf(acc[mf][nf][1], 0.0f);
            float y10 = fmaxf(acc[mf][nf][2], 0.0f);
            float y11 = fmaxf(acc[mf][nf][3], 0.0f);
#pragma unroll
            for (int ch = 0; ch < 3; ch++) {
                float w0 = bias[BI_RW + col0 * 3 + ch], w1 = bias[BI_RW + col1 * 3 + ch];
                p[mf * 2 + 0][ch] += y00 * w0 + y01 * w1;
                p[mf * 2 + 1][ch] += y10 * w0 + y11 * w1;
            }
        }
#pragma unroll
    for (int r = 0; r < 8; r++)
#pragma unroll
        for (int ch = 0; ch < 3; ch++) {
            p[r][ch] += __shfl_xor_sync(0xffffffffu, p[r][ch], 1);
            p[r][ch] += __shfl_xor_sync(0xffffffffu, p[r][ch], 2);
        }

    float* part = (float*)(smem + SB_BOTT);
    __syncthreads();
    if (tq == 0) {
#pragma unroll
        for (int mf = 0; mf < 4; mf++)
#pragma unroll
            for (int h = 0; h < 2; h++) {
                int row = m0 + mf * 16 + g + 8 * h;
                int r = mf * 2 + h;
                part[(wn * 128 + row) * 3 + 0] = p[r][0];
                part[(wn * 128 + row) * 3 + 1] = p[r][1];
                part[(wn * 128 + row) * 3 + 2] = p[r][2];
            }
    }
    __syncthreads();
    if (t < 384) {
        const int m = t / 3, ch = t - m * 3;
        float v = bias[BI_RB + ch];
#pragma unroll
        for (int gq = 0; gq < 8; gq++) v += part[(gq * 128 + m) * 3 + ch];
        float sg = 1.0f / (1.0f + expf(-v));
        out_rgb[(base + (size_t)m) * 3 + ch] = sg * 1.002f - 0.001f;
    }
}

// ---------------------------------------------------------------- launch
extern "C" void kernel_launch(void* const* d_in, const int* in_sizes, int n_in,
                              void* d_out, int out_size)
{
    const float*  coords   = (const float*)d_in[0];
    const float*  viewdirs = (const float*)d_in[2];
    const float4* emb      = (const float4*)d_in[3];
    const float*  w1       = (const float*)d_in[4];
    const float*  b1       = (const float*)d_in[5];
    const float*  w2       = (const float*)d_in[6];
    const float*  b2       = (const float*)d_in[7];
    const float*  lin0_w   = (const float*)d_in[8];
    const float*  lin0_b   = (const float*)d_in[9];
    const float*  lin1_w   = (const float*)d_in[10];
    const float*  lin1_b   = (const float*)d_in[11];
    const float*  rgb_w    = (const float*)d_in[12];
    const float*  rgb_b    = (const float*)d_in[13];

    float* dout    = (float*)d_out;
    float* density = dout;
    float* rgb     = dout + NPTS;

    __half *feats, *U1T, *U2T;
    __nv_bfloat16 *W0T, *W1T;
    cudaGetSymbolAddress((void**)&feats, g_feats);
    cudaGetSymbolAddress((void**)&W0T, g_W0T);
    cudaGetSymbolAddress((void**)&W1T, g_W1T);
    cudaGetSymbolAddress((void**)&U1T, g_U1T);
    cudaGetSymbolAddress((void**)&U2T, g_U2T);

    cudaFuncSetAttribute(kernF, cudaFuncAttributeMaxDynamicSharedMemorySize,
                         SMEMF_BYTES);

    prepW<<<544, 256>>>(lin0_w, lin1_w, w1, w2, W0T, W1T, U1T, U2T);
    kernA<<<NPTS / 128, 256>>>(coords, emb, feats);
    kernF<<<NTILES, 512, SMEMF_BYTES>>>(feats, viewdirs, U1T, U2T, b1, b2,
                                        W0T, W1T, lin0_b, lin1_b,
                                        rgb_w, rgb_b, density, rgb);
}